// round 8
// baseline (speedup 1.0000x reference)
#include <cuda_runtime.h>
#include <math_constants.h>

#define Bk 8
#define Nk 1024
#define Ck 256
#define Hk 4
#define Dk 64

#define OUT_ELEMS (Bk * Nk * Ck)      /* 2097152 : p_attn starts after this   */
#define MASK_ELEMS (Bk * Nk * Nk)     /* 8388608                              */

// mask dtype kind: 0 = uint8 (raw bool bytes), 1 = int32, 2 = float32
__device__ int g_mask_kind;

// ---------------------------------------------------------------------------
// Probe: classify mask buffer dtype from its first 16 32-bit words.
//  int32 bools  -> every word is 0 or 1
//  float32 bools-> every word is 0x00000000 or 0x3F800000
//  uint8 bools  -> random 0/1 bytes; neither pattern holds
// ---------------------------------------------------------------------------
__global__ void k_probe(const unsigned int* __restrict__ mask_words)
{
    int i32ok = 1, f32ok = 1;
#pragma unroll
    for (int i = 0; i < 16; i++) {
        unsigned int x = mask_words[i];
        if (x != 0u && x != 1u)           i32ok = 0;
        if (x != 0u && x != 0x3F800000u)  f32ok = 0;
    }
    g_mask_kind = i32ok ? 1 : (f32ok ? 2 : 0);
}

// ---------------------------------------------------------------------------
// Convert mask (whatever dtype) -> uint8 0/1 into mcvt (scratch in d_out).
// 4 elements per thread.
// ---------------------------------------------------------------------------
__global__ __launch_bounds__(256) void k_maskcvt(
    const void* __restrict__ mask, unsigned char* __restrict__ mcvt)
{
    const int e0 = (blockIdx.x * 256 + threadIdx.x) * 4;
    if (e0 >= MASK_ELEMS) return;
    const int kind = g_mask_kind;
    uchar4 o;
    if (kind == 1) {
        int4 v = *(const int4*)((const int*)mask + e0);
        o.x = v.x != 0; o.y = v.y != 0; o.z = v.z != 0; o.w = v.w != 0;
    } else if (kind == 2) {
        float4 v = *(const float4*)((const float*)mask + e0);
        o.x = v.x != 0.f; o.y = v.y != 0.f; o.z = v.z != 0.f; o.w = v.w != 0.f;
    } else {
        uchar4 v = *(const uchar4*)((const unsigned char*)mask + e0);
        o.x = v.x != 0; o.y = v.y != 0; o.z = v.z != 0; o.w = v.w != 0;
    }
    *(uchar4*)(mcvt + e0) = o;
}

// ---------------------------------------------------------------------------
// Kernel 1: raw masked scaled scores -> P buffer
// S[h,b,n,m] = (q[b,n,h*64:].k[b,m,h*64:] + dis[b,n,m]) / 8 ; mask -> -inf
// 64x64 block tile, K=64, 256 threads, 4x4 per thread.
// Both operand tiles stored K-major so inner loop = 2x LDS.128 + 16 FFMA.
// ---------------------------------------------------------------------------
__global__ __launch_bounds__(256) void k_scores(
    const float* __restrict__ q, const float* __restrict__ kmat,
    const unsigned char* __restrict__ mask, const float* __restrict__ dis,
    float* __restrict__ P)
{
    __shared__ float Qt[64][68];      // [k][row]  transposed, pad 4
    __shared__ float Kt[64][68];      // [k][col]  transposed

    const int n0 = blockIdx.x * 64;
    const int m0 = blockIdx.y * 64;
    const int z  = blockIdx.z;        // h*8 + b
    const int h  = z >> 3;
    const int b  = z & 7;

    const int tid  = threadIdx.x;
    const int lrow = tid >> 4;        // 0..15
    const int c4   = tid & 15;        // 0..15

    const float* qb = q    + ((size_t)b * Nk + n0) * Ck + h * Dk;
    const float* kb = kmat + ((size_t)b * Nk + m0) * Ck + h * Dk;

#pragma unroll
    for (int it = 0; it < 4; it++) {
        const int r = lrow + it * 16;
        float4 vq = *(const float4*)(qb + (size_t)r * Ck + c4 * 4);
        Qt[c4 * 4 + 0][r] = vq.x;
        Qt[c4 * 4 + 1][r] = vq.y;
        Qt[c4 * 4 + 2][r] = vq.z;
        Qt[c4 * 4 + 3][r] = vq.w;
        float4 vk = *(const float4*)(kb + (size_t)r * Ck + c4 * 4);
        Kt[c4 * 4 + 0][r] = vk.x;
        Kt[c4 * 4 + 1][r] = vk.y;
        Kt[c4 * 4 + 2][r] = vk.z;
        Kt[c4 * 4 + 3][r] = vk.w;
    }
    __syncthreads();

    const int ty = tid >> 4;
    const int tx = tid & 15;

    float acc[4][4] = {};
#pragma unroll
    for (int p = 0; p < 64; p++) {
        float4 qf = *(const float4*)&Qt[p][ty * 4];   // warp broadcast
        float4 kf = *(const float4*)&Kt[p][tx * 4];
        const float qv[4] = {qf.x, qf.y, qf.z, qf.w};
        const float kv[4] = {kf.x, kf.y, kf.z, kf.w};
#pragma unroll
        for (int i = 0; i < 4; i++)
#pragma unroll
            for (int j = 0; j < 4; j++)
                acc[i][j] = fmaf(qv[i], kv[j], acc[i][j]);
    }

    const float scale = 0.125f;
    const size_t base_dm = ((size_t)b * Nk + (n0 + ty * 4)) * Nk + m0 + tx * 4;
    const size_t base_p  = ((size_t)(h * Bk + b) * Nk + (n0 + ty * 4)) * Nk + m0 + tx * 4;

#pragma unroll
    for (int i = 0; i < 4; i++) {
        float4 dv = *(const float4*)(dis + base_dm + (size_t)i * Nk);
        uchar4 mv = *(const uchar4*)(mask + base_dm + (size_t)i * Nk);
        float4 sv;
        sv.x = (acc[i][0] + dv.x) * scale;
        sv.y = (acc[i][1] + dv.y) * scale;
        sv.z = (acc[i][2] + dv.z) * scale;
        sv.w = (acc[i][3] + dv.w) * scale;
        if (mv.x) sv.x = -CUDART_INF_F;
        if (mv.y) sv.y = -CUDART_INF_F;
        if (mv.z) sv.z = -CUDART_INF_F;
        if (mv.w) sv.w = -CUDART_INF_F;
        *(float4*)(P + base_p + (size_t)i * Nk) = sv;
    }
}

// ---------------------------------------------------------------------------
// Kernel 2: in-place row softmax over last dim (1024). One block per row.
// ---------------------------------------------------------------------------
__global__ __launch_bounds__(256) void k_softmax(float* __restrict__ P)
{
    __shared__ float redm[8];
    __shared__ float reds[8];
    const size_t rowbase = (size_t)blockIdx.x * Nk;
    const int tid = threadIdx.x;

    float4 v = *(float4*)(P + rowbase + tid * 4);

    float m = fmaxf(fmaxf(v.x, v.y), fmaxf(v.z, v.w));
#pragma unroll
    for (int o = 16; o > 0; o >>= 1)
        m = fmaxf(m, __shfl_xor_sync(0xffffffffu, m, o));
    if ((tid & 31) == 0) redm[tid >> 5] = m;
    __syncthreads();
    float rowmax = redm[0];
#pragma unroll
    for (int i = 1; i < 8; i++) rowmax = fmaxf(rowmax, redm[i]);

    v.x = __expf(v.x - rowmax);
    v.y = __expf(v.y - rowmax);
    v.z = __expf(v.z - rowmax);
    v.w = __expf(v.w - rowmax);

    float s = v.x + v.y + v.z + v.w;
#pragma unroll
    for (int o = 16; o > 0; o >>= 1)
        s += __shfl_xor_sync(0xffffffffu, s, o);
    if ((tid & 31) == 0) reds[tid >> 5] = s;
    __syncthreads();
    float rowsum = 0.f;
#pragma unroll
    for (int i = 0; i < 8; i++) rowsum += reds[i];

    const float inv = 1.0f / rowsum;
    v.x *= inv; v.y *= inv; v.z *= inv; v.w *= inv;
    *(float4*)(P + rowbase + tid * 4) = v;
}

// ---------------------------------------------------------------------------
// Kernel 3: out[b,n,h*64+d] = sum_m P[h,b,n,m] * v[b,m,h*64+d]
// Per (h,b): GEMM 1024 x 64 x 1024. P tile transposed for LDS.128 broadcast.
// ---------------------------------------------------------------------------
__global__ __launch_bounds__(256) void k_pv(
    const float* __restrict__ P, const float* __restrict__ vmat,
    float* __restrict__ out)
{
    __shared__ float Pt[64][68];      // [m][n] transposed, padded
    __shared__ float Vs[64][64];      // [m][d] natural

    const int n0 = blockIdx.x * 64;
    const int z  = blockIdx.y;
    const int h  = z >> 3;
    const int b  = z & 7;

    const int tid  = threadIdx.x;
    const int lrow = tid >> 4;
    const int c4   = tid & 15;
    const int ty   = tid >> 4;
    const int tx   = tid & 15;

    const float* Pb = P    + ((size_t)(h * Bk + b) * Nk + n0) * Nk;
    const float* vb = vmat + (size_t)b * Nk * Ck + h * Dk;

    float acc[4][4] = {};

    for (int m0 = 0; m0 < Nk; m0 += 64) {
#pragma unroll
        for (int it = 0; it < 4; it++) {
            const int r = lrow + it * 16;
            float4 pv = *(const float4*)(Pb + (size_t)r * Nk + m0 + c4 * 4);
            Pt[c4 * 4 + 0][r] = pv.x;
            Pt[c4 * 4 + 1][r] = pv.y;
            Pt[c4 * 4 + 2][r] = pv.z;
            Pt[c4 * 4 + 3][r] = pv.w;
            *(float4*)&Vs[r][c4 * 4] =
                *(const float4*)(vb + (size_t)(m0 + r) * Ck + c4 * 4);
        }
        __syncthreads();

#pragma unroll
        for (int p = 0; p < 64; p++) {
            float4 pf = *(const float4*)&Pt[p][ty * 4];   // broadcast
            float4 vf = *(const float4*)&Vs[p][tx * 4];
            const float pr[4] = {pf.x, pf.y, pf.z, pf.w};
            const float vv[4] = {vf.x, vf.y, vf.z, vf.w};
#pragma unroll
            for (int i = 0; i < 4; i++)
#pragma unroll
                for (int j = 0; j < 4; j++)
                    acc[i][j] = fmaf(pr[i], vv[j], acc[i][j]);
        }
        __syncthreads();
    }

#pragma unroll
    for (int i = 0; i < 4; i++) {
        float4 o;
        o.x = acc[i][0]; o.y = acc[i][1]; o.z = acc[i][2]; o.w = acc[i][3];
        *(float4*)(out + ((size_t)b * Nk + n0 + ty * 4 + i) * Ck + h * Dk + tx * 4) = o;
    }
}

// ---------------------------------------------------------------------------
extern "C" void kernel_launch(void* const* d_in, const int* in_sizes, int n_in,
                              void* d_out, int out_size)
{
    (void)in_sizes; (void)n_in; (void)out_size;

    const float* q    = (const float*)d_in[0];
    const float* kmat = (const float*)d_in[1];
    const float* vmat = (const float*)d_in[2];
    const void*  mask = d_in[3];
    const float* dis  = (const float*)d_in[4];

    float* out  = (float*)d_out;              // [8,1024,256]
    float* Pbuf = (float*)d_out + OUT_ELEMS;  // [4,8,1024,1024]

    // out region (8 MB) doubles as uint8 mask scratch until k_pv overwrites it.
    unsigned char* mcvt = (unsigned char*)d_out;

    k_probe<<<1, 1>>>((const unsigned int*)mask);
    k_maskcvt<<<(MASK_ELEMS / 4 + 255) / 256, 256>>>(mask, mcvt);

    dim3 g1(Nk / 64, Nk / 64, Hk * Bk);
    k_scores<<<g1, 256>>>(q, kmat, mcvt, dis, Pbuf);

    k_softmax<<<Hk * Bk * Nk, 256>>>(Pbuf);

    dim3 g3(Nk / 64, Hk * Bk);
    k_pv<<<g3, 256>>>(Pbuf, vmat, out);
}

// round 10
// speedup vs baseline: 1.0382x; 1.0382x over previous
#include <cuda_runtime.h>
#include <cuda_bf16.h>
#include <math_constants.h>
#include <mma.h>
#include <cstdint>

using namespace nvcuda;

#define Bk 8
#define Nk 1024
#define Ck 256
#define Hk 4
#define Dk 64

#define OUT_ELEMS (Bk * Nk * Ck)      /* 2097152 : p_attn starts after this   */
#define MASK_ELEMS (Bk * Nk * Nk)     /* 8388608                              */

// bf16 tile leading dim (elements): 64 + 8 pad -> 144B row stride, conflict-spread
#define LDT 72
// f32 acc staging leading dim
#define LDA 68
// smem byte offsets (4 bf16 tiles of 64*72*2 = 9216 B each; acc f32 overlays tile 0/1)
#define SM_T0 0
#define SM_T1 9216
#define SM_T2 18432
#define SM_T3 27648
#define SM_TOTAL 36864

// mask dtype kind: 0 = uint8 (raw bool bytes), 1 = int32, 2 = float32
__device__ int g_mask_kind;

__global__ void k_probe(const unsigned int* __restrict__ mask_words)
{
    int i32ok = 1, f32ok = 1;
#pragma unroll
    for (int i = 0; i < 16; i++) {
        unsigned int x = mask_words[i];
        if (x != 0u && x != 1u)           i32ok = 0;
        if (x != 0u && x != 0x3F800000u)  f32ok = 0;
    }
    g_mask_kind = i32ok ? 1 : (f32ok ? 2 : 0);
}

__global__ __launch_bounds__(256) void k_maskcvt(
    const void* __restrict__ mask, unsigned char* __restrict__ mcvt)
{
    const int e0 = (blockIdx.x * 256 + threadIdx.x) * 4;
    if (e0 >= MASK_ELEMS) return;
    const int kind = g_mask_kind;
    uchar4 o;
    if (kind == 1) {
        int4 v = *(const int4*)((const int*)mask + e0);
        o.x = v.x != 0; o.y = v.y != 0; o.z = v.z != 0; o.w = v.w != 0;
    } else if (kind == 2) {
        float4 v = *(const float4*)((const float*)mask + e0);
        o.x = v.x != 0.f; o.y = v.y != 0.f; o.z = v.z != 0.f; o.w = v.w != 0.f;
    } else {
        uchar4 v = *(const uchar4*)((const unsigned char*)mask + e0);
        o.x = v.x != 0; o.y = v.y != 0; o.z = v.z != 0; o.w = v.w != 0;
    }
    *(uchar4*)(mcvt + e0) = o;
}

// split one float4 into hi/lo bf16 quads and store at tile[r*LDT + c]
__device__ __forceinline__ void split_store(
    __nv_bfloat16* hi, __nv_bfloat16* lo, int r, int c, float4 v)
{
    __nv_bfloat16 hx = __float2bfloat16(v.x);
    __nv_bfloat16 hy = __float2bfloat16(v.y);
    __nv_bfloat16 hz = __float2bfloat16(v.z);
    __nv_bfloat16 hw = __float2bfloat16(v.w);
    __nv_bfloat16 lx = __float2bfloat16(v.x - __bfloat162float(hx));
    __nv_bfloat16 ly = __float2bfloat16(v.y - __bfloat162float(hy));
    __nv_bfloat16 lz = __float2bfloat16(v.z - __bfloat162float(hz));
    __nv_bfloat16 lw = __float2bfloat16(v.w - __bfloat162float(hw));
    __nv_bfloat162* ph = (__nv_bfloat162*)(hi + r * LDT + c);
    __nv_bfloat162* pl = (__nv_bfloat162*)(lo + r * LDT + c);
    ph[0] = __nv_bfloat162(hx, hy);
    ph[1] = __nv_bfloat162(hz, hw);
    pl[0] = __nv_bfloat162(lx, ly);
    pl[1] = __nv_bfloat162(lz, lw);
}

// ===========================================================================
// Kernel 1 (WMMA bf16 split-3): S = (QK^T + dis)/8, mask -> -inf, into P.
// Block: 64(n) x 64(m), K=64. 128 threads = 4 warps; warp w owns rows 16w..16w+15.
// ===========================================================================
__global__ __launch_bounds__(128) void k_scores_w(
    const float* __restrict__ q, const float* __restrict__ kmat,
    const unsigned char* __restrict__ mask, const float* __restrict__ dis,
    float* __restrict__ P)
{
    extern __shared__ char sm[];
    __nv_bfloat16* Qhi = (__nv_bfloat16*)(sm + SM_T0);
    __nv_bfloat16* Qlo = (__nv_bfloat16*)(sm + SM_T1);
    __nv_bfloat16* Khi = (__nv_bfloat16*)(sm + SM_T2);
    __nv_bfloat16* Klo = (__nv_bfloat16*)(sm + SM_T3);
    float* accbuf = (float*)sm;           // overlays Qhi/Qlo after compute

    const int n0 = blockIdx.x * 64;
    const int m0 = blockIdx.y * 64;
    const int z  = blockIdx.z;            // h*8 + b
    const int h  = z >> 3;
    const int b  = z & 7;
    const int tid = threadIdx.x;
    const int wid = tid >> 5;

    // fill both tile pairs: 64 rows x 16 float4-cols each
    for (int idx = tid; idx < 64 * 16; idx += 128) {
        const int r  = idx >> 4;
        const int c4 = (idx & 15) * 4;
        float4 vq = *(const float4*)(q    + ((size_t)b * Nk + n0 + r) * Ck + h * Dk + c4);
        split_store(Qhi, Qlo, r, c4, vq);
        float4 vk = *(const float4*)(kmat + ((size_t)b * Nk + m0 + r) * Ck + h * Dk + c4);
        split_store(Khi, Klo, r, c4, vk);
    }
    __syncthreads();

    wmma::fragment<wmma::accumulator, 16, 16, 16, float> acc[4];
#pragma unroll
    for (int nt = 0; nt < 4; nt++) wmma::fill_fragment(acc[nt], 0.0f);

    const __nv_bfloat16* Ab[3] = {Qhi, Qhi, Qlo};
    const __nv_bfloat16* Bb[3] = {Khi, Klo, Khi};
#pragma unroll
    for (int p = 0; p < 3; p++) {
#pragma unroll
        for (int kt = 0; kt < 4; kt++) {
            wmma::fragment<wmma::matrix_a, 16, 16, 16, __nv_bfloat16, wmma::row_major> a;
            wmma::load_matrix_sync(a, Ab[p] + (wid * 16) * LDT + kt * 16, LDT);
#pragma unroll
            for (int nt = 0; nt < 4; nt++) {
                // B = K^T: element (k, m) at K[m][k] -> col_major from &K[nt*16][kt*16]
                wmma::fragment<wmma::matrix_b, 16, 16, 16, __nv_bfloat16, wmma::col_major> bf;
                wmma::load_matrix_sync(bf, Bb[p] + (nt * 16) * LDT + kt * 16, LDT);
                wmma::mma_sync(acc[nt], a, bf, acc[nt]);
            }
        }
    }
    __syncthreads();   // all warps done reading tiles before acc overwrite
#pragma unroll
    for (int nt = 0; nt < 4; nt++)
        wmma::store_matrix_sync(accbuf + (wid * 16) * LDA + nt * 16, acc[nt],
                                LDA, wmma::mem_row_major);
    __syncthreads();

    // epilogue
    const float scale = 0.125f;
    for (int idx = tid; idx < 64 * 16; idx += 128) {
        const int r  = idx >> 4;
        const int c4 = (idx & 15) * 4;
        const size_t dm = ((size_t)b * Nk + n0 + r) * Nk + m0 + c4;
        float4 s = *(const float4*)(accbuf + r * LDA + c4);
        float4 dv = *(const float4*)(dis + dm);
        uchar4 mv = *(const uchar4*)(mask + dm);
        float4 sv;
        sv.x = (s.x + dv.x) * scale;
        sv.y = (s.y + dv.y) * scale;
        sv.z = (s.z + dv.z) * scale;
        sv.w = (s.w + dv.w) * scale;
        if (mv.x) sv.x = -CUDART_INF_F;
        if (mv.y) sv.y = -CUDART_INF_F;
        if (mv.z) sv.z = -CUDART_INF_F;
        if (mv.w) sv.w = -CUDART_INF_F;
        *(float4*)(P + ((size_t)(h * Bk + b) * Nk + n0 + r) * Nk + m0 + c4) = sv;
    }
}

// ---------------------------------------------------------------------------
// Kernel 2: in-place row softmax over last dim (1024). One block per row.
// ---------------------------------------------------------------------------
__global__ __launch_bounds__(256) void k_softmax(float* __restrict__ P)
{
    __shared__ float redm[8];
    __shared__ float reds[8];
    const size_t rowbase = (size_t)blockIdx.x * Nk;
    const int tid = threadIdx.x;

    float4 v = *(float4*)(P + rowbase + tid * 4);

    float m = fmaxf(fmaxf(v.x, v.y), fmaxf(v.z, v.w));
#pragma unroll
    for (int o = 16; o > 0; o >>= 1)
        m = fmaxf(m, __shfl_xor_sync(0xffffffffu, m, o));
    if ((tid & 31) == 0) redm[tid >> 5] = m;
    __syncthreads();
    float rowmax = redm[0];
#pragma unroll
    for (int i = 1; i < 8; i++) rowmax = fmaxf(rowmax, redm[i]);

    v.x = __expf(v.x - rowmax);
    v.y = __expf(v.y - rowmax);
    v.z = __expf(v.z - rowmax);
    v.w = __expf(v.w - rowmax);

    float s = v.x + v.y + v.z + v.w;
#pragma unroll
    for (int o = 16; o > 0; o >>= 1)
        s += __shfl_xor_sync(0xffffffffu, s, o);
    if ((tid & 31) == 0) reds[tid >> 5] = s;
    __syncthreads();
    float rowsum = 0.f;
#pragma unroll
    for (int i = 0; i < 8; i++) rowsum += reds[i];

    const float inv = 1.0f / rowsum;
    v.x *= inv; v.y *= inv; v.z *= inv; v.w *= inv;
    *(float4*)(P + rowbase + tid * 4) = v;
}

// ===========================================================================
// Kernel 3 (WMMA bf16 split-3): out[b,n,h*64+d] = sum_m P[h,b,n,m]*v[b,m,h*64+d]
// Block: 64(n) x 64(d), K(m) = 1024 in 64-chunks. 4 warps as above.
// ===========================================================================
__global__ __launch_bounds__(128) void k_pv_w(
    const float* __restrict__ P, const float* __restrict__ vmat,
    float* __restrict__ out)
{
    extern __shared__ char sm[];
    __nv_bfloat16* Phi = (__nv_bfloat16*)(sm + SM_T0);
    __nv_bfloat16* Plo = (__nv_bfloat16*)(sm + SM_T1);
    __nv_bfloat16* Vhi = (__nv_bfloat16*)(sm + SM_T2);
    __nv_bfloat16* Vlo = (__nv_bfloat16*)(sm + SM_T3);
    float* accbuf = (float*)sm;

    const int n0 = blockIdx.x * 64;
    const int z  = blockIdx.y;            // h*8 + b
    const int h  = z >> 3;
    const int b  = z & 7;
    const int tid = threadIdx.x;
    const int wid = tid >> 5;

    const float* Pb = P    + ((size_t)(h * Bk + b) * Nk + n0) * Nk;
    const float* vb = vmat + (size_t)b * Nk * Ck + h * Dk;

    wmma::fragment<wmma::accumulator, 16, 16, 16, float> acc[4];
#pragma unroll
    for (int nt = 0; nt < 4; nt++) wmma::fill_fragment(acc[nt], 0.0f);

    for (int m0 = 0; m0 < Nk; m0 += 64) {
        for (int idx = tid; idx < 64 * 16; idx += 128) {
            const int r  = idx >> 4;
            const int c4 = (idx & 15) * 4;
            float4 pv = *(const float4*)(Pb + (size_t)r * Nk + m0 + c4);
            split_store(Phi, Plo, r, c4, pv);
            float4 vv = *(const float4*)(vb + (size_t)(m0 + r) * Ck + c4);
            split_store(Vhi, Vlo, r, c4, vv);
        }
        __syncthreads();

        const __nv_bfloat16* Ab[3] = {Phi, Phi, Plo};
        const __nv_bfloat16* Bb[3] = {Vhi, Vlo, Vhi};
#pragma unroll
        for (int p = 0; p < 3; p++) {
#pragma unroll
            for (int kt = 0; kt < 4; kt++) {
                wmma::fragment<wmma::matrix_a, 16, 16, 16, __nv_bfloat16, wmma::row_major> a;
                wmma::load_matrix_sync(a, Ab[p] + (wid * 16) * LDT + kt * 16, LDT);
#pragma unroll
                for (int nt = 0; nt < 4; nt++) {
                    // B(row=m,col=d) at V[m][d] -> row_major from &V[kt*16][nt*16]
                    wmma::fragment<wmma::matrix_b, 16, 16, 16, __nv_bfloat16, wmma::row_major> bf;
                    wmma::load_matrix_sync(bf, Bb[p] + (kt * 16) * LDT + nt * 16, LDT);
                    wmma::mma_sync(acc[nt], a, bf, acc[nt]);
                }
            }
        }
        __syncthreads();   // done with this chunk's tiles
    }

#pragma unroll
    for (int nt = 0; nt < 4; nt++)
        wmma::store_matrix_sync(accbuf + (wid * 16) * LDA + nt * 16, acc[nt],
                                LDA, wmma::mem_row_major);
    __syncthreads();

    for (int idx = tid; idx < 64 * 16; idx += 128) {
        const int r  = idx >> 4;
        const int c4 = (idx & 15) * 4;
        float4 o = *(const float4*)(accbuf + r * LDA + c4);
        *(float4*)(out + ((size_t)b * Nk + n0 + r) * Ck + h * Dk + c4) = o;
    }
}

// ---------------------------------------------------------------------------
extern "C" void kernel_launch(void* const* d_in, const int* in_sizes, int n_in,
                              void* d_out, int out_size)
{
    (void)in_sizes; (void)n_in; (void)out_size;

    const float* q    = (const float*)d_in[0];
    const float* kmat = (const float*)d_in[1];
    const float* vmat = (const float*)d_in[2];
    const void*  mask = d_in[3];
    const float* dis  = (const float*)d_in[4];

    float* out  = (float*)d_out;              // [8,1024,256]
    float* Pbuf = (float*)d_out + OUT_ELEMS;  // [4,8,1024,1024]

    unsigned char* mcvt = (unsigned char*)d_out;  // scratch until k_pv_w writes

    k_probe<<<1, 1>>>((const unsigned int*)mask);
    k_maskcvt<<<(MASK_ELEMS / 4 + 255) / 256, 256>>>(mask, mcvt);

    dim3 g1(Nk / 64, Nk / 64, Hk * Bk);
    k_scores_w<<<g1, 128, SM_TOTAL>>>(q, kmat, mcvt, dis, Pbuf);

    k_softmax<<<Hk * Bk * Nk, 256>>>(Pbuf);

    dim3 g3(Nk / 64, Hk * Bk);
    k_pv_w<<<g3, 128, SM_TOTAL>>>(Pbuf, vmat, out);
}

// round 11
// speedup vs baseline: 1.1506x; 1.1083x over previous
#include <cuda_runtime.h>
#include <cuda_bf16.h>
#include <math_constants.h>
#include <mma.h>
#include <cstdint>

using namespace nvcuda;

#define Bk 8
#define Nk 1024
#define Ck 256
#define Hk 4
#define Dk 64

#define OUT_ELEMS (Bk * Nk * Ck)      /* 2097152 : p_attn starts after this   */
#define MASK_ELEMS (Bk * Nk * Nk)     /* 8388608                              */

#define LDT 72                        /* bf16 tile ld: 64 + 8 pad             */

// precomputed bf16 split operands (static scratch — allowed)
__device__ __nv_bfloat16 g_qhi[OUT_ELEMS];
__device__ __nv_bfloat16 g_qlo[OUT_ELEMS];
__device__ __nv_bfloat16 g_khi[OUT_ELEMS];
__device__ __nv_bfloat16 g_klo[OUT_ELEMS];
__device__ __nv_bfloat16 g_vhi[OUT_ELEMS];
__device__ __nv_bfloat16 g_vlo[OUT_ELEMS];

// mask dtype kind: 0 = uint8 (raw bool bytes), 1 = int32, 2 = float32
__device__ int g_mask_kind;

__global__ void k_probe(const unsigned int* __restrict__ mask_words)
{
    int i32ok = 1, f32ok = 1;
#pragma unroll
    for (int i = 0; i < 16; i++) {
        unsigned int x = mask_words[i];
        if (x != 0u && x != 1u)           i32ok = 0;
        if (x != 0u && x != 0x3F800000u)  f32ok = 0;
    }
    g_mask_kind = i32ok ? 1 : (f32ok ? 2 : 0);
}

__global__ __launch_bounds__(256) void k_maskcvt(
    const void* __restrict__ mask, unsigned char* __restrict__ mcvt)
{
    const int e0 = (blockIdx.x * 256 + threadIdx.x) * 4;
    if (e0 >= MASK_ELEMS) return;
    const int kind = g_mask_kind;
    uchar4 o;
    if (kind == 1) {
        int4 v = *(const int4*)((const int*)mask + e0);
        o.x = v.x != 0; o.y = v.y != 0; o.z = v.z != 0; o.w = v.w != 0;
    } else if (kind == 2) {
        float4 v = *(const float4*)((const float*)mask + e0);
        o.x = v.x != 0.f; o.y = v.y != 0.f; o.z = v.z != 0.f; o.w = v.w != 0.f;
    } else {
        uchar4 v = *(const uchar4*)((const unsigned char*)mask + e0);
        o.x = v.x != 0; o.y = v.y != 0; o.z = v.z != 0; o.w = v.w != 0;
    }
    *(uchar4*)(mcvt + e0) = o;
}

// ---------------------------------------------------------------------------
// One-shot fp32 -> (hi, lo) bf16 split for a whole tensor.
// ---------------------------------------------------------------------------
__global__ __launch_bounds__(256) void k_cvt(
    const float* __restrict__ src,
    __nv_bfloat16* __restrict__ hi, __nv_bfloat16* __restrict__ lo)
{
    const int i4 = blockIdx.x * 256 + threadIdx.x;          // float4 index
    if (i4 >= OUT_ELEMS / 4) return;
    float4 v = ((const float4*)src)[i4];
    __nv_bfloat16 hx = __float2bfloat16(v.x);
    __nv_bfloat16 hy = __float2bfloat16(v.y);
    __nv_bfloat16 hz = __float2bfloat16(v.z);
    __nv_bfloat16 hw = __float2bfloat16(v.w);
    __nv_bfloat162 h01(hx, hy), h23(hz, hw);
    __nv_bfloat162 l01(__float2bfloat16(v.x - __bfloat162float(hx)),
                       __float2bfloat16(v.y - __bfloat162float(hy)));
    __nv_bfloat162 l23(__float2bfloat16(v.z - __bfloat162float(hz)),
                       __float2bfloat16(v.w - __bfloat162float(hw)));
    uint2 hp = make_uint2(*(uint32_t*)&h01, *(uint32_t*)&h23);
    uint2 lp = make_uint2(*(uint32_t*)&l01, *(uint32_t*)&l23);
    ((uint2*)hi)[i4] = hp;
    ((uint2*)lo)[i4] = lp;
}

// ===========================================================================
// Kernel 1 (WMMA bf16 split-3): S = (QK^T + dis)/8, mask -> -inf, into P.
// Tile 128(n) x 128(m), K=64. 256 threads = 8 warps; warp w rows 16w..16w+15.
// ===========================================================================
#define S1_QHI 0
#define S1_QLO 18432
#define S1_KHI 36864
#define S1_KLO 55296
#define S1_TOTAL 73728
#define S1_LDA 132                     /* f32 acc staging ld (128+4) */

__global__ __launch_bounds__(256) void k_scores_w(
    const unsigned char* __restrict__ mask, const float* __restrict__ dis,
    float* __restrict__ P)
{
    extern __shared__ char sm[];
    __nv_bfloat16* Qhi = (__nv_bfloat16*)(sm + S1_QHI);
    __nv_bfloat16* Qlo = (__nv_bfloat16*)(sm + S1_QLO);
    __nv_bfloat16* Khi = (__nv_bfloat16*)(sm + S1_KHI);
    __nv_bfloat16* Klo = (__nv_bfloat16*)(sm + S1_KLO);
    float* accbuf = (float*)sm;        // 128 x S1_LDA overlay (67.6 KB)

    const int n0 = blockIdx.x * 128;
    const int m0 = blockIdx.y * 128;
    const int z  = blockIdx.z;         // h*8 + b
    const int h  = z >> 3;
    const int b  = z & 7;
    const int tid = threadIdx.x;
    const int wid = tid >> 5;

    // fill: 128 rows x 8 uint4 per plane (pure copies of precomputed bf16)
    for (int idx = tid; idx < 128 * 8; idx += 256) {
        const int r = idx >> 3;
        const int u = idx & 7;
        const size_t gq = ((size_t)b * Nk + n0 + r) * Ck + h * Dk + u * 8;
        const size_t gk = ((size_t)b * Nk + m0 + r) * Ck + h * Dk + u * 8;
        *(uint4*)(Qhi + r * LDT + u * 8) = *(const uint4*)(g_qhi + gq);
        *(uint4*)(Qlo + r * LDT + u * 8) = *(const uint4*)(g_qlo + gq);
        *(uint4*)(Khi + r * LDT + u * 8) = *(const uint4*)(g_khi + gk);
        *(uint4*)(Klo + r * LDT + u * 8) = *(const uint4*)(g_klo + gk);
    }
    __syncthreads();

    wmma::fragment<wmma::accumulator, 16, 16, 16, float> acc[8];
#pragma unroll
    for (int nt = 0; nt < 8; nt++) wmma::fill_fragment(acc[nt], 0.0f);

    const __nv_bfloat16* Ab[3] = {Qhi, Qhi, Qlo};
    const __nv_bfloat16* Bb[3] = {Khi, Klo, Khi};
#pragma unroll
    for (int p = 0; p < 3; p++) {
#pragma unroll
        for (int kt = 0; kt < 4; kt++) {
            wmma::fragment<wmma::matrix_a, 16, 16, 16, __nv_bfloat16, wmma::row_major> a;
            wmma::load_matrix_sync(a, Ab[p] + (wid * 16) * LDT + kt * 16, LDT);
#pragma unroll
            for (int nt = 0; nt < 8; nt++) {
                wmma::fragment<wmma::matrix_b, 16, 16, 16, __nv_bfloat16, wmma::col_major> bf;
                wmma::load_matrix_sync(bf, Bb[p] + (nt * 16) * LDT + kt * 16, LDT);
                wmma::mma_sync(acc[nt], a, bf, acc[nt]);
            }
        }
    }
    __syncthreads();
#pragma unroll
    for (int nt = 0; nt < 8; nt++)
        wmma::store_matrix_sync(accbuf + (wid * 16) * S1_LDA + nt * 16, acc[nt],
                                S1_LDA, wmma::mem_row_major);
    __syncthreads();

    const float scale = 0.125f;
    for (int idx = tid; idx < 128 * 32; idx += 256) {
        const int r  = idx >> 5;
        const int c4 = (idx & 31) * 4;
        const size_t dm = ((size_t)b * Nk + n0 + r) * Nk + m0 + c4;
        float4 s = *(const float4*)(accbuf + r * S1_LDA + c4);
        float4 dv = *(const float4*)(dis + dm);
        uchar4 mv = *(const uchar4*)(mask + dm);
        float4 sv;
        sv.x = (s.x + dv.x) * scale;
        sv.y = (s.y + dv.y) * scale;
        sv.z = (s.z + dv.z) * scale;
        sv.w = (s.w + dv.w) * scale;
        if (mv.x) sv.x = -CUDART_INF_F;
        if (mv.y) sv.y = -CUDART_INF_F;
        if (mv.z) sv.z = -CUDART_INF_F;
        if (mv.w) sv.w = -CUDART_INF_F;
        *(float4*)(P + ((size_t)(h * Bk + b) * Nk + n0 + r) * Nk + m0 + c4) = sv;
    }
}

// ---------------------------------------------------------------------------
// Kernel 2: in-place row softmax over last dim (1024). One block per row.
// ---------------------------------------------------------------------------
__global__ __launch_bounds__(256) void k_softmax(float* __restrict__ P)
{
    __shared__ float redm[8];
    __shared__ float reds[8];
    const size_t rowbase = (size_t)blockIdx.x * Nk;
    const int tid = threadIdx.x;

    float4 v = *(float4*)(P + rowbase + tid * 4);

    float m = fmaxf(fmaxf(v.x, v.y), fmaxf(v.z, v.w));
#pragma unroll
    for (int o = 16; o > 0; o >>= 1)
        m = fmaxf(m, __shfl_xor_sync(0xffffffffu, m, o));
    if ((tid & 31) == 0) redm[tid >> 5] = m;
    __syncthreads();
    float rowmax = redm[0];
#pragma unroll
    for (int i = 1; i < 8; i++) rowmax = fmaxf(rowmax, redm[i]);

    v.x = __expf(v.x - rowmax);
    v.y = __expf(v.y - rowmax);
    v.z = __expf(v.z - rowmax);
    v.w = __expf(v.w - rowmax);

    float s = v.x + v.y + v.z + v.w;
#pragma unroll
    for (int o = 16; o > 0; o >>= 1)
        s += __shfl_xor_sync(0xffffffffu, s, o);
    if ((tid & 31) == 0) reds[tid >> 5] = s;
    __syncthreads();
    float rowsum = 0.f;
#pragma unroll
    for (int i = 0; i < 8; i++) rowsum += reds[i];

    const float inv = 1.0f / rowsum;
    v.x *= inv; v.y *= inv; v.z *= inv; v.w *= inv;
    *(float4*)(P + rowbase + tid * 4) = v;
}

// ===========================================================================
// Kernel 3 (WMMA bf16 split-3): out = P @ V.  Tile 128(n) x 64(d), K=1024.
// 256 threads = 8 warps. P converted inline (once per element), V copied.
// ===========================================================================
#define S3_PHI 0
#define S3_PLO 18432
#define S3_VHI 36864
#define S3_VLO 46080
#define S3_TOTAL 55296
#define S3_LDA 68

__global__ __launch_bounds__(256) void k_pv_w(
    const float* __restrict__ P, float* __restrict__ out)
{
    extern __shared__ char sm[];
    __nv_bfloat16* Phi = (__nv_bfloat16*)(sm + S3_PHI);
    __nv_bfloat16* Plo = (__nv_bfloat16*)(sm + S3_PLO);
    __nv_bfloat16* Vhi = (__nv_bfloat16*)(sm + S3_VHI);
    __nv_bfloat16* Vlo = (__nv_bfloat16*)(sm + S3_VLO);
    float* accbuf = (float*)sm;

    const int n0 = blockIdx.x * 128;
    const int z  = blockIdx.y;         // h*8 + b
    const int h  = z >> 3;
    const int b  = z & 7;
    const int tid = threadIdx.x;
    const int wid = tid >> 5;

    const float* Pb = P + ((size_t)(h * Bk + b) * Nk + n0) * Nk;

    wmma::fragment<wmma::accumulator, 16, 16, 16, float> acc[4];
#pragma unroll
    for (int nt = 0; nt < 4; nt++) wmma::fill_fragment(acc[nt], 0.0f);

    for (int m0 = 0; m0 < Nk; m0 += 64) {
        // P tile: 128 rows x 64 cols, split inline (each element exactly once)
        for (int idx = tid; idx < 128 * 16; idx += 256) {
            const int r  = idx >> 4;
            const int c4 = (idx & 15) * 4;
            float4 v = *(const float4*)(Pb + (size_t)r * Nk + m0 + c4);
            __nv_bfloat16 hx = __float2bfloat16(v.x);
            __nv_bfloat16 hy = __float2bfloat16(v.y);
            __nv_bfloat16 hz = __float2bfloat16(v.z);
            __nv_bfloat16 hw = __float2bfloat16(v.w);
            __nv_bfloat162 h01(hx, hy), h23(hz, hw);
            __nv_bfloat162 l01(__float2bfloat16(v.x - __bfloat162float(hx)),
                               __float2bfloat16(v.y - __bfloat162float(hy)));
            __nv_bfloat162 l23(__float2bfloat16(v.z - __bfloat162float(hz)),
                               __float2bfloat16(v.w - __bfloat162float(hw)));
            __nv_bfloat162* ph = (__nv_bfloat162*)(Phi + r * LDT + c4);
            __nv_bfloat162* pl = (__nv_bfloat162*)(Plo + r * LDT + c4);
            ph[0] = h01; ph[1] = h23;
            pl[0] = l01; pl[1] = l23;
        }
        // V tile: 64 rows x 64 cols, pure copy of precomputed bf16
        for (int idx = tid; idx < 64 * 8; idx += 256) {
            const int r = idx >> 3;
            const int u = idx & 7;
            const size_t gv = ((size_t)b * Nk + m0 + r) * Ck + h * Dk + u * 8;
            *(uint4*)(Vhi + r * LDT + u * 8) = *(const uint4*)(g_vhi + gv);
            *(uint4*)(Vlo + r * LDT + u * 8) = *(const uint4*)(g_vlo + gv);
        }
        __syncthreads();

        const __nv_bfloat16* Ab[3] = {Phi, Phi, Plo};
        const __nv_bfloat16* Bb[3] = {Vhi, Vlo, Vhi};
#pragma unroll
        for (int p = 0; p < 3; p++) {
#pragma unroll
            for (int kt = 0; kt < 4; kt++) {
                wmma::fragment<wmma::matrix_a, 16, 16, 16, __nv_bfloat16, wmma::row_major> a;
                wmma::load_matrix_sync(a, Ab[p] + (wid * 16) * LDT + kt * 16, LDT);
#pragma unroll
                for (int nt = 0; nt < 4; nt++) {
                    wmma::fragment<wmma::matrix_b, 16, 16, 16, __nv_bfloat16, wmma::row_major> bf;
                    wmma::load_matrix_sync(bf, Bb[p] + (kt * 16) * LDT + nt * 16, LDT);
                    wmma::mma_sync(acc[nt], a, bf, acc[nt]);
                }
            }
        }
        __syncthreads();
    }

#pragma unroll
    for (int nt = 0; nt < 4; nt++)
        wmma::store_matrix_sync(accbuf + (wid * 16) * S3_LDA + nt * 16, acc[nt],
                                S3_LDA, wmma::mem_row_major);
    __syncthreads();

    for (int idx = tid; idx < 128 * 16; idx += 256) {
        const int r  = idx >> 4;
        const int c4 = (idx & 15) * 4;
        float4 o = *(const float4*)(accbuf + r * S3_LDA + c4);
        *(float4*)(out + ((size_t)b * Nk + n0 + r) * Ck + h * Dk + c4) = o;
    }
}

// ---------------------------------------------------------------------------
extern "C" void kernel_launch(void* const* d_in, const int* in_sizes, int n_in,
                              void* d_out, int out_size)
{
    (void)in_sizes; (void)n_in; (void)out_size;

    const float* q    = (const float*)d_in[0];
    const float* kmat = (const float*)d_in[1];
    const float* vmat = (const float*)d_in[2];
    const void*  mask = d_in[3];
    const float* dis  = (const float*)d_in[4];

    float* out  = (float*)d_out;              // [8,1024,256]
    float* Pbuf = (float*)d_out + OUT_ELEMS;  // [4,8,1024,1024]
    unsigned char* mcvt = (unsigned char*)d_out;  // scratch until k_pv_w writes

    static int attr_set = 0;
    if (!attr_set) {
        cudaFuncSetAttribute(k_scores_w,
            cudaFuncAttributeMaxDynamicSharedMemorySize, S1_TOTAL);
        cudaFuncSetAttribute(k_pv_w,
            cudaFuncAttributeMaxDynamicSharedMemorySize, S3_TOTAL);
        attr_set = 1;
    }

    k_probe<<<1, 1>>>((const unsigned int*)mask);
    k_maskcvt<<<(MASK_ELEMS / 4 + 255) / 256, 256>>>(mask, mcvt);

    __nv_bfloat16 *qhi, *qlo, *khi, *klo, *vhi, *vlo;
    cudaGetSymbolAddress((void**)&qhi, g_qhi);
    cudaGetSymbolAddress((void**)&qlo, g_qlo);
    cudaGetSymbolAddress((void**)&khi, g_khi);
    cudaGetSymbolAddress((void**)&klo, g_klo);
    cudaGetSymbolAddress((void**)&vhi, g_vhi);
    cudaGetSymbolAddress((void**)&vlo, g_vlo);

    const int cvt_blocks = (OUT_ELEMS / 4 + 255) / 256;
    k_cvt<<<cvt_blocks, 256>>>(q,    qhi, qlo);
    k_cvt<<<cvt_blocks, 256>>>(kmat, khi, klo);
    k_cvt<<<cvt_blocks, 256>>>(vmat, vhi, vlo);

    dim3 g1(Nk / 128, Nk / 128, Hk * Bk);
    k_scores_w<<<g1, 256, S1_TOTAL>>>(mcvt, dis, Pbuf);

    k_softmax<<<Hk * Bk * Nk, 256>>>(Pbuf);

    dim3 g3(Nk / 128, Hk * Bk);
    k_pv_w<<<g3, 256, S3_TOTAL>>>(Pbuf, out);
}

// round 12
// speedup vs baseline: 1.1596x; 1.0078x over previous
#include <cuda_runtime.h>
#include <cuda_bf16.h>
#include <math_constants.h>
#include <mma.h>
#include <cstdint>

using namespace nvcuda;

#define Bk 8
#define Nk 1024
#define Ck 256
#define Hk 4
#define Dk 64

#define OUT_ELEMS (Bk * Nk * Ck)      /* 2097152 : p_attn starts after this   */

#define LDT 72                        /* bf16 tile ld: 64 + 8 pad             */

// precomputed bf16 split operands (static scratch — allowed)
__device__ __nv_bfloat16 g_qhi[OUT_ELEMS];
__device__ __nv_bfloat16 g_qlo[OUT_ELEMS];
__device__ __nv_bfloat16 g_khi[OUT_ELEMS];
__device__ __nv_bfloat16 g_klo[OUT_ELEMS];
__device__ __nv_bfloat16 g_vhi[OUT_ELEMS];
__device__ __nv_bfloat16 g_vlo[OUT_ELEMS];

// mask dtype kind: 0 = uint8 (raw bool bytes), 1 = int32, 2 = float32
__device__ int g_mask_kind;

__global__ void k_probe(const unsigned int* __restrict__ mask_words)
{
    int i32ok = 1, f32ok = 1;
#pragma unroll
    for (int i = 0; i < 16; i++) {
        unsigned int x = mask_words[i];
        if (x != 0u && x != 1u)           i32ok = 0;
        if (x != 0u && x != 0x3F800000u)  f32ok = 0;
    }
    g_mask_kind = i32ok ? 1 : (f32ok ? 2 : 0);
}

// ---------------------------------------------------------------------------
// One-shot fp32 -> (hi, lo) bf16 split for a whole tensor.
// ---------------------------------------------------------------------------
__global__ __launch_bounds__(256) void k_cvt(
    const float* __restrict__ src,
    __nv_bfloat16* __restrict__ hi, __nv_bfloat16* __restrict__ lo)
{
    const int i4 = blockIdx.x * 256 + threadIdx.x;          // float4 index
    if (i4 >= OUT_ELEMS / 4) return;
    float4 v = ((const float4*)src)[i4];
    __nv_bfloat16 hx = __float2bfloat16(v.x);
    __nv_bfloat16 hy = __float2bfloat16(v.y);
    __nv_bfloat16 hz = __float2bfloat16(v.z);
    __nv_bfloat16 hw = __float2bfloat16(v.w);
    __nv_bfloat162 h01(hx, hy), h23(hz, hw);
    __nv_bfloat162 l01(__float2bfloat16(v.x - __bfloat162float(hx)),
                       __float2bfloat16(v.y - __bfloat162float(hy)));
    __nv_bfloat162 l23(__float2bfloat16(v.z - __bfloat162float(hz)),
                       __float2bfloat16(v.w - __bfloat162float(hw)));
    uint2 hp = make_uint2(*(uint32_t*)&h01, *(uint32_t*)&h23);
    uint2 lp = make_uint2(*(uint32_t*)&l01, *(uint32_t*)&l23);
    ((uint2*)hi)[i4] = hp;
    ((uint2*)lo)[i4] = lp;
}

// ===========================================================================
// Kernel 1 (WMMA bf16 split-3): S = (QK^T + dis)/8, mask -> -inf, into P.
// Tile 128(n) x 128(m), K=64. 256 threads = 8 warps; warp w rows 16w..16w+15.
// Mask read inline with runtime dtype dispatch (g_mask_kind).
// ===========================================================================
#define S1_QHI 0
#define S1_QLO 18432
#define S1_KHI 36864
#define S1_KLO 55296
#define S1_TOTAL 73728
#define S1_LDA 132                     /* f32 acc staging ld (128+4) */

__global__ __launch_bounds__(256) void k_scores_w(
    const void* __restrict__ mask, const float* __restrict__ dis,
    float* __restrict__ P)
{
    extern __shared__ char sm[];
    __nv_bfloat16* Qhi = (__nv_bfloat16*)(sm + S1_QHI);
    __nv_bfloat16* Qlo = (__nv_bfloat16*)(sm + S1_QLO);
    __nv_bfloat16* Khi = (__nv_bfloat16*)(sm + S1_KHI);
    __nv_bfloat16* Klo = (__nv_bfloat16*)(sm + S1_KLO);
    float* accbuf = (float*)sm;        // 128 x S1_LDA overlay (67.6 KB)

    const int n0 = blockIdx.x * 128;
    const int m0 = blockIdx.y * 128;
    const int z  = blockIdx.z;         // h*8 + b
    const int h  = z >> 3;
    const int b  = z & 7;
    const int tid = threadIdx.x;
    const int wid = tid >> 5;

    // fill: 128 rows x 8 uint4 per plane (pure copies of precomputed bf16)
    for (int idx = tid; idx < 128 * 8; idx += 256) {
        const int r = idx >> 3;
        const int u = idx & 7;
        const size_t gq = ((size_t)b * Nk + n0 + r) * Ck + h * Dk + u * 8;
        const size_t gk = ((size_t)b * Nk + m0 + r) * Ck + h * Dk + u * 8;
        *(uint4*)(Qhi + r * LDT + u * 8) = *(const uint4*)(g_qhi + gq);
        *(uint4*)(Qlo + r * LDT + u * 8) = *(const uint4*)(g_qlo + gq);
        *(uint4*)(Khi + r * LDT + u * 8) = *(const uint4*)(g_khi + gk);
        *(uint4*)(Klo + r * LDT + u * 8) = *(const uint4*)(g_klo + gk);
    }
    __syncthreads();

    wmma::fragment<wmma::accumulator, 16, 16, 16, float> acc[8];
#pragma unroll
    for (int nt = 0; nt < 8; nt++) wmma::fill_fragment(acc[nt], 0.0f);

    const __nv_bfloat16* Ab[3] = {Qhi, Qhi, Qlo};
    const __nv_bfloat16* Bb[3] = {Khi, Klo, Khi};
#pragma unroll
    for (int p = 0; p < 3; p++) {
#pragma unroll
        for (int kt = 0; kt < 4; kt++) {
            wmma::fragment<wmma::matrix_a, 16, 16, 16, __nv_bfloat16, wmma::row_major> a;
            wmma::load_matrix_sync(a, Ab[p] + (wid * 16) * LDT + kt * 16, LDT);
#pragma unroll
            for (int nt = 0; nt < 8; nt++) {
                wmma::fragment<wmma::matrix_b, 16, 16, 16, __nv_bfloat16, wmma::col_major> bf;
                wmma::load_matrix_sync(bf, Bb[p] + (nt * 16) * LDT + kt * 16, LDT);
                wmma::mma_sync(acc[nt], a, bf, acc[nt]);
            }
        }
    }
    __syncthreads();
#pragma unroll
    for (int nt = 0; nt < 8; nt++)
        wmma::store_matrix_sync(accbuf + (wid * 16) * S1_LDA + nt * 16, acc[nt],
                                S1_LDA, wmma::mem_row_major);
    __syncthreads();

    const float scale = 0.125f;
    const int kind = g_mask_kind;
    for (int idx = tid; idx < 128 * 32; idx += 256) {
        const int r  = idx >> 5;
        const int c4 = (idx & 31) * 4;
        const size_t dm = ((size_t)b * Nk + n0 + r) * Nk + m0 + c4;
        float4 s = *(const float4*)(accbuf + r * S1_LDA + c4);
        float4 dv = *(const float4*)(dis + dm);
        int mx, my, mz, mw;
        if (kind == 1) {
            int4 mv = *(const int4*)((const int*)mask + dm);
            mx = mv.x != 0; my = mv.y != 0; mz = mv.z != 0; mw = mv.w != 0;
        } else if (kind == 2) {
            float4 mv = *(const float4*)((const float*)mask + dm);
            mx = mv.x != 0.f; my = mv.y != 0.f; mz = mv.z != 0.f; mw = mv.w != 0.f;
        } else {
            uchar4 mv = *(const uchar4*)((const unsigned char*)mask + dm);
            mx = mv.x; my = mv.y; mz = mv.z; mw = mv.w;
        }
        float4 sv;
        sv.x = (s.x + dv.x) * scale;
        sv.y = (s.y + dv.y) * scale;
        sv.z = (s.z + dv.z) * scale;
        sv.w = (s.w + dv.w) * scale;
        if (mx) sv.x = -CUDART_INF_F;
        if (my) sv.y = -CUDART_INF_F;
        if (mz) sv.z = -CUDART_INF_F;
        if (mw) sv.w = -CUDART_INF_F;
        *(float4*)(P + ((size_t)(h * Bk + b) * Nk + n0 + r) * Nk + m0 + c4) = sv;
    }
}

// ---------------------------------------------------------------------------
// Kernel 2: in-place row softmax over last dim (1024). One block per row.
// ---------------------------------------------------------------------------
__global__ __launch_bounds__(256) void k_softmax(float* __restrict__ P)
{
    __shared__ float redm[8];
    __shared__ float reds[8];
    const size_t rowbase = (size_t)blockIdx.x * Nk;
    const int tid = threadIdx.x;

    float4 v = *(float4*)(P + rowbase + tid * 4);

    float m = fmaxf(fmaxf(v.x, v.y), fmaxf(v.z, v.w));
#pragma unroll
    for (int o = 16; o > 0; o >>= 1)
        m = fmaxf(m, __shfl_xor_sync(0xffffffffu, m, o));
    if ((tid & 31) == 0) redm[tid >> 5] = m;
    __syncthreads();
    float rowmax = redm[0];
#pragma unroll
    for (int i = 1; i < 8; i++) rowmax = fmaxf(rowmax, redm[i]);

    v.x = __expf(v.x - rowmax);
    v.y = __expf(v.y - rowmax);
    v.z = __expf(v.z - rowmax);
    v.w = __expf(v.w - rowmax);

    float s = v.x + v.y + v.z + v.w;
#pragma unroll
    for (int o = 16; o > 0; o >>= 1)
        s += __shfl_xor_sync(0xffffffffu, s, o);
    if ((tid & 31) == 0) reds[tid >> 5] = s;
    __syncthreads();
    float rowsum = 0.f;
#pragma unroll
    for (int i = 0; i < 8; i++) rowsum += reds[i];

    const float inv = 1.0f / rowsum;
    v.x *= inv; v.y *= inv; v.z *= inv; v.w *= inv;
    *(float4*)(P + rowbase + tid * 4) = v;
}

// ===========================================================================
// Kernel 3 (WMMA bf16 split-3): out = P @ V.  Tile 64(n) x 64(d), K=1024.
// 128 threads = 4 warps; warp w rows 16w..16w+15. Grid 512 CTAs.
// ===========================================================================
#define S3_PHI 0
#define S3_PLO 9216
#define S3_VHI 18432
#define S3_VLO 27648
#define S3_TOTAL 36864
#define S3_LDA 68

__global__ __launch_bounds__(128) void k_pv_w(
    const float* __restrict__ P, float* __restrict__ out)
{
    extern __shared__ char sm[];
    __nv_bfloat16* Phi = (__nv_bfloat16*)(sm + S3_PHI);
    __nv_bfloat16* Plo = (__nv_bfloat16*)(sm + S3_PLO);
    __nv_bfloat16* Vhi = (__nv_bfloat16*)(sm + S3_VHI);
    __nv_bfloat16* Vlo = (__nv_bfloat16*)(sm + S3_VLO);
    float* accbuf = (float*)sm;

    const int n0 = blockIdx.x * 64;
    const int z  = blockIdx.y;         // h*8 + b
    const int h  = z >> 3;
    const int b  = z & 7;
    const int tid = threadIdx.x;
    const int wid = tid >> 5;

    const float* Pb = P + ((size_t)(h * Bk + b) * Nk + n0) * Nk;

    wmma::fragment<wmma::accumulator, 16, 16, 16, float> acc[4];
#pragma unroll
    for (int nt = 0; nt < 4; nt++) wmma::fill_fragment(acc[nt], 0.0f);

    for (int m0 = 0; m0 < Nk; m0 += 64) {
        // P tile: 64 rows x 64 cols, split inline (each element exactly once)
        for (int idx = tid; idx < 64 * 16; idx += 128) {
            const int r  = idx >> 4;
            const int c4 = (idx & 15) * 4;
            float4 v = *(const float4*)(Pb + (size_t)r * Nk + m0 + c4);
            __nv_bfloat16 hx = __float2bfloat16(v.x);
            __nv_bfloat16 hy = __float2bfloat16(v.y);
            __nv_bfloat16 hz = __float2bfloat16(v.z);
            __nv_bfloat16 hw = __float2bfloat16(v.w);
            __nv_bfloat162 h01(hx, hy), h23(hz, hw);
            __nv_bfloat162 l01(__float2bfloat16(v.x - __bfloat162float(hx)),
                               __float2bfloat16(v.y - __bfloat162float(hy)));
            __nv_bfloat162 l23(__float2bfloat16(v.z - __bfloat162float(hz)),
                               __float2bfloat16(v.w - __bfloat162float(hw)));
            __nv_bfloat162* ph = (__nv_bfloat162*)(Phi + r * LDT + c4);
            __nv_bfloat162* pl = (__nv_bfloat162*)(Plo + r * LDT + c4);
            ph[0] = h01; ph[1] = h23;
            pl[0] = l01; pl[1] = l23;
        }
        // V tile: 64 rows x 64 cols, pure copy of precomputed bf16
        for (int idx = tid; idx < 64 * 8; idx += 128) {
            const int r = idx >> 3;
            const int u = idx & 7;
            const size_t gv = ((size_t)b * Nk + m0 + r) * Ck + h * Dk + u * 8;
            *(uint4*)(Vhi + r * LDT + u * 8) = *(const uint4*)(g_vhi + gv);
            *(uint4*)(Vlo + r * LDT + u * 8) = *(const uint4*)(g_vlo + gv);
        }
        __syncthreads();

        const __nv_bfloat16* Ab[3] = {Phi, Phi, Plo};
        const __nv_bfloat16* Bb[3] = {Vhi, Vlo, Vhi};
#pragma unroll
        for (int p = 0; p < 3; p++) {
#pragma unroll
            for (int kt = 0; kt < 4; kt++) {
                wmma::fragment<wmma::matrix_a, 16, 16, 16, __nv_bfloat16, wmma::row_major> a;
                wmma::load_matrix_sync(a, Ab[p] + (wid * 16) * LDT + kt * 16, LDT);
#pragma unroll
                for (int nt = 0; nt < 4; nt++) {
                    wmma::fragment<wmma::matrix_b, 16, 16, 16, __nv_bfloat16, wmma::row_major> bf;
                    wmma::load_matrix_sync(bf, Bb[p] + (kt * 16) * LDT + nt * 16, LDT);
                    wmma::mma_sync(acc[nt], a, bf, acc[nt]);
                }
            }
        }
        __syncthreads();
    }

#pragma unroll
    for (int nt = 0; nt < 4; nt++)
        wmma::store_matrix_sync(accbuf + (wid * 16) * S3_LDA + nt * 16, acc[nt],
                                S3_LDA, wmma::mem_row_major);
    __syncthreads();

    for (int idx = tid; idx < 64 * 16; idx += 128) {
        const int r  = idx >> 4;
        const int c4 = (idx & 15) * 4;
        float4 o = *(const float4*)(accbuf + r * S3_LDA + c4);
        *(float4*)(out + ((size_t)b * Nk + n0 + r) * Ck + h * Dk + c4) = o;
    }
}

// ---------------------------------------------------------------------------
extern "C" void kernel_launch(void* const* d_in, const int* in_sizes, int n_in,
                              void* d_out, int out_size)
{
    (void)in_sizes; (void)n_in; (void)out_size;

    const float* q    = (const float*)d_in[0];
    const float* kmat = (const float*)d_in[1];
    const float* vmat = (const float*)d_in[2];
    const void*  mask = d_in[3];
    const float* dis  = (const float*)d_in[4];

    float* out  = (float*)d_out;              // [8,1024,256]
    float* Pbuf = (float*)d_out + OUT_ELEMS;  // [4,8,1024,1024]

    static int attr_set = 0;
    if (!attr_set) {
        cudaFuncSetAttribute(k_scores_w,
            cudaFuncAttributeMaxDynamicSharedMemorySize, S1_TOTAL);
        cudaFuncSetAttribute(k_pv_w,
            cudaFuncAttributeMaxDynamicSharedMemorySize, S3_TOTAL);
        attr_set = 1;
    }

    __nv_bfloat16 *qhi, *qlo, *khi, *klo, *vhi, *vlo;
    cudaGetSymbolAddress((void**)&qhi, g_qhi);
    cudaGetSymbolAddress((void**)&qlo, g_qlo);
    cudaGetSymbolAddress((void**)&khi, g_khi);
    cudaGetSymbolAddress((void**)&klo, g_klo);
    cudaGetSymbolAddress((void**)&vhi, g_vhi);
    cudaGetSymbolAddress((void**)&vlo, g_vlo);

    const int cvt_blocks = (OUT_ELEMS / 4 + 255) / 256;

    // Order chosen so k_scores_w is the 4th launch (profiler window).
    k_probe<<<1, 1>>>((const unsigned int*)mask);
    k_cvt<<<cvt_blocks, 256>>>(q,    qhi, qlo);
    k_cvt<<<cvt_blocks, 256>>>(kmat, khi, klo);

    dim3 g1(Nk / 128, Nk / 128, Hk * Bk);
    k_scores_w<<<g1, 256, S1_TOTAL>>>(mask, dis, Pbuf);

    k_softmax<<<Hk * Bk * Nk, 256>>>(Pbuf);

    k_cvt<<<cvt_blocks, 256>>>(vmat, vhi, vlo);

    dim3 g3(Nk / 64, Hk * Bk);
    k_pv_w<<<g3, 128, S3_TOTAL>>>(Pbuf, out);
}